// round 1
// baseline (speedup 1.0000x reference)
#include <cuda_runtime.h>

// Problem shape (fixed by setup_inputs): X (32, 64, 25, 2, 16, 16) fp32.
#define S_N    32      // batch N
#define TVM    3200    // 64*25*2 matrices per sample
#define NE     256     // 16*16 elements per matrix
#define CHUNKS 32      // K1 partial-reduce chunks per sample
#define CHUNK_M 100    // TVM / CHUNKS

// ---------------- device scratch (no allocations allowed) ----------------
__device__ float g_partial[S_N * CHUNKS * NE];   // 1 MB partial sums
__device__ float g_xmean[S_N * NE];              // per-sample means
__device__ float g_C[NE];                        // invsqrt(mean) for the big transform

// =========================================================================
// K1: partial reduction of X over the 3200 inner matrices (per sample).
// grid (32, 32), 256 threads; each block sums 100 matrices elementwise.
// =========================================================================
__global__ __launch_bounds__(256) void k_partial(const float* __restrict__ X) {
    int s = blockIdx.x, c = blockIdx.y;
    int t = threadIdx.x;
    const float* p = X + ((size_t)s * TVM + (size_t)c * CHUNK_M) * NE + t;
    float acc = 0.f;
#pragma unroll 10
    for (int m = 0; m < CHUNK_M; ++m) acc += p[(size_t)m * NE];
    g_partial[(s * CHUNKS + c) * NE + t] = acc;
}

// =========================================================================
// Block-level (128-thread) 16x16 matrix helpers. Convention: every helper
// finishes with __syncthreads() after its writes; outputs never alias inputs
// unless stated.
// =========================================================================
__device__ __forceinline__ void bmm(float* C, const float* A, const float* B, int t) {
    float r0, r1;
    {
        int i = t >> 4, j = t & 15;
        float a = 0.f;
#pragma unroll
        for (int k = 0; k < 16; ++k) a += A[i * 16 + k] * B[k * 16 + j];
        r0 = a;
    }
    {
        int idx = t + 128; int i = idx >> 4, j = idx & 15;
        float a = 0.f;
#pragma unroll
        for (int k = 0; k < 16; ++k) a += A[i * 16 + k] * B[k * 16 + j];
        r1 = a;
    }
    C[t] = r0; C[t + 128] = r1;
    __syncthreads();
}

__device__ __forceinline__ float bsum_all(float v, int t, volatile float* red) {
    red[t] = v; __syncthreads();
    for (int s = 64; s > 0; s >>= 1) { if (t < s) red[t] += red[t + s]; __syncthreads(); }
    float r = red[0]; __syncthreads();
    return r;
}

__device__ __forceinline__ float b_norm2_diffI(const float* A, int t, volatile float* red) {
    float acc = 0.f;
#pragma unroll
    for (int e = 0; e < 2; ++e) {
        int idx = t + e * 128; int i = idx >> 4, j = idx & 15;
        float v = A[idx] - (i == j ? 1.f : 0.f); acc += v * v;
    }
    return bsum_all(acc, t, red);
}

__device__ __forceinline__ float b_norm2(const float* A, int t, volatile float* red) {
    float v0 = A[t], v1 = A[t + 128];
    return bsum_all(v0 * v0 + v1 * v1, t, red);
}

__device__ float b_rowmax(const float* A, int t, volatile float* red) {
    float s_ = 0.f;
    if (t < 16) {
        for (int k = 0; k < 16; ++k) s_ += fabsf(A[t * 16 + k]);
    }
    red[t] = s_; __syncthreads();
    if (t == 0) {
        float m = red[0];
        for (int i = 1; i < 16; ++i) m = fmaxf(m, red[i]);
        red[0] = m;
    }
    __syncthreads();
    float r = red[0]; __syncthreads();
    return r;
}

// Coupled Newton-Schulz: Ys = sqrt(A), Zs = invsqrt(A). Temps T, Yb, Zb.
// All six buffers distinct.
__device__ void b_sqrtinv(const float* A, float* Ys, float* Zs,
                          float* T, float* Yb, float* Zb, int t, volatile float* red) {
    float rho = b_rowmax(A, t, red);       // rho >= lambda_max, spectrum of A/rho in (0,1]
    float sc = 1.f / rho;
#pragma unroll
    for (int e = 0; e < 2; ++e) {
        int idx = t + e * 128; int i = idx >> 4, j = idx & 15;
        Ys[idx] = A[idx] * sc; Zs[idx] = (i == j) ? 1.f : 0.f;
    }
    __syncthreads();
    float* Y = Ys; float* Z = Zs; float* Y2 = Yb; float* Z2 = Zb;
    for (int it = 0; it < 30; ++it) {
        bmm(T, Z, Y, t);                           // T = Z*Y
        float e2 = b_norm2_diffI(T, t, red);
        if (e2 < 1e-11f) break;
#pragma unroll
        for (int e = 0; e < 2; ++e) {
            int idx = t + e * 128; int i = idx >> 4, j = idx & 15;
            T[idx] = 0.5f * ((i == j ? 3.f : 0.f) - T[idx]);
        }
        __syncthreads();
        bmm(Y2, Y, T, t);
        bmm(Z2, T, Z, t);
        float* tmp;
        tmp = Y; Y = Y2; Y2 = tmp;
        tmp = Z; Z = Z2; Z2 = tmp;
    }
    float f = sqrtf(rho), fi = rsqrtf(rho);
    float y0 = Y[t] * f, y1 = Y[t + 128] * f;
    float z0 = Z[t] * fi, z1 = Z[t + 128] * fi;
    __syncthreads();
    Ys[t] = y0; Ys[t + 128] = y1; Zs[t] = z0; Zs[t + 128] = z1;
    __syncthreads();
}

// logm(B) in place (B SPD). Inverse scaling-and-squaring + Mercator series.
__device__ void b_logm_inplace(float* B, float* t1, float* t2, float* t3,
                               float* t4, float* t5, int t, volatile float* red) {
    int jsq = 0;
    while (jsq < 8) {
        float d2 = b_norm2_diffI(B, t, red);
        if (d2 < 0.09f) break;                     // ||B - I||_F < 0.3
        b_sqrtinv(B, t1, t2, t3, t4, t5, t, red);  // t1 = sqrt(B)
        float a0 = t1[t], a1 = t1[t + 128]; __syncthreads();
        B[t] = a0; B[t + 128] = a1; __syncthreads();
        jsq++;
    }
    // E = B - I (t1); L accumulates into B; P = E (t2)
#pragma unroll
    for (int e = 0; e < 2; ++e) {
        int idx = t + e * 128; int i = idx >> 4, j = idx & 15;
        float v = B[idx] - (i == j ? 1.f : 0.f);
        t1[idx] = v; t2[idx] = v; B[idx] = v;
    }
    __syncthreads();
    float* P = t2; float* P2 = t3;
    float sgn = 1.f;
    for (int k = 2; k <= 18; ++k) {
        bmm(P2, P, t1, t);                 // P2 = E^k
        sgn = -sgn;
        float coef = sgn / (float)k;
        float pn = 0.f;
#pragma unroll
        for (int e = 0; e < 2; ++e) {
            int idx = t + e * 128;
            float v = P2[idx]; B[idx] += coef * v; pn += v * v;
        }
        pn = bsum_all(pn, t, red);
        float* tmp = P; P = P2; P2 = tmp;
        if (pn < 1e-13f * (float)(k * k)) break;   // ||term|| < ~3e-7
    }
    float f = (float)(1 << jsq);
    float l0 = B[t] * f, l1 = B[t + 128] * f; __syncthreads();
    B[t] = l0; B[t + 128] = l1; __syncthreads();
}

// expm(A) -> R (A is modified by scaling). Scaling-and-squaring + Taylor.
__device__ void b_expm(float* A, float* R, float* P, float* P2, int t, volatile float* red) {
    float n2 = b_norm2(A, t, red);
    int j = 0;
    while (n2 > 0.0625f && j < 30) {
        A[t] *= 0.5f; A[t + 128] *= 0.5f; __syncthreads();
        n2 *= 0.25f; j++;
    }
#pragma unroll
    for (int e = 0; e < 2; ++e) {
        int idx = t + e * 128; int i = idx >> 4, jj = idx & 15;
        float v = A[idx];
        R[idx] = v + (i == jj ? 1.f : 0.f);
        P[idx] = v;
    }
    __syncthreads();
    float* Pp = P; float* Pq = P2;
    for (int k = 2; k <= 12; ++k) {
        bmm(Pq, Pp, A, t);
        float ik = 1.f / (float)k;
#pragma unroll
        for (int e = 0; e < 2; ++e) {
            int idx = t + e * 128;
            float v = Pq[idx] * ik; Pq[idx] = v; R[idx] += v;
        }
        __syncthreads();
        float* tmp = Pp; Pp = Pq; Pq = tmp;
    }
    for (int q = 0; q < j; ++q) {
        bmm(Pq, R, R, t);
        float a0 = Pq[t], a1 = Pq[t + 128]; __syncthreads();
        R[t] = a0; R[t + 128] = a1; __syncthreads();
    }
}

// =========================================================================
// Warp-level variants (for the 32-matrix logm stage, 4 warps in parallel)
// =========================================================================
__device__ __forceinline__ float wsum(float v) {
#pragma unroll
    for (int o = 16; o; o >>= 1) v += __shfl_xor_sync(0xffffffffu, v, o);
    return v;
}

__device__ __forceinline__ void wmm(float* C, const float* A, const float* B, int lane) {
    float r[8];
#pragma unroll
    for (int e = 0; e < 8; ++e) {
        int idx = e * 32 + lane; int i = idx >> 4, j = idx & 15;
        float a = 0.f;
#pragma unroll
        for (int k = 0; k < 16; ++k) a += A[i * 16 + k] * B[k * 16 + j];
        r[e] = a;
    }
    __syncwarp();
#pragma unroll
    for (int e = 0; e < 8; ++e) C[e * 32 + lane] = r[e];
    __syncwarp();
}

__device__ __forceinline__ float w_norm2_diffI(const float* A, int lane) {
    float acc = 0.f;
#pragma unroll
    for (int e = 0; e < 8; ++e) {
        int idx = e * 32 + lane; int i = idx >> 4, j = idx & 15;
        float v = A[idx] - (i == j ? 1.f : 0.f); acc += v * v;
    }
    return wsum(acc);
}

__device__ void w_sqrt_inplace(float* B, float* Y, float* Z, float* T,
                               float* Y2, float* Z2, int lane) {
    float s_ = 0.f;
    if (lane < 16) {
        for (int k = 0; k < 16; ++k) s_ += fabsf(B[lane * 16 + k]);
    }
#pragma unroll
    for (int o = 16; o; o >>= 1) s_ = fmaxf(s_, __shfl_xor_sync(0xffffffffu, s_, o));
    float rho = s_, sc = 1.f / rho;
#pragma unroll
    for (int e = 0; e < 8; ++e) {
        int idx = e * 32 + lane; int i = idx >> 4, j = idx & 15;
        Y[idx] = B[idx] * sc; Z[idx] = (i == j) ? 1.f : 0.f;
    }
    __syncwarp();
    float* y = Y; float* z = Z; float* y2 = Y2; float* z2 = Z2;
    for (int it = 0; it < 30; ++it) {
        wmm(T, z, y, lane);
        float e2 = w_norm2_diffI(T, lane);
        if (e2 < 1e-11f) break;
#pragma unroll
        for (int e = 0; e < 8; ++e) {
            int idx = e * 32 + lane; int i = idx >> 4, j = idx & 15;
            T[idx] = 0.5f * ((i == j ? 3.f : 0.f) - T[idx]);
        }
        __syncwarp();
        wmm(y2, y, T, lane);
        wmm(z2, T, z, lane);
        float* tm = y; y = y2; y2 = tm;
        tm = z; z = z2; z2 = tm;
    }
    float f = sqrtf(rho);
    float r[8];
#pragma unroll
    for (int e = 0; e < 8; ++e) r[e] = y[e * 32 + lane] * f;
    __syncwarp();
#pragma unroll
    for (int e = 0; e < 8; ++e) B[e * 32 + lane] = r[e];
    __syncwarp();
}

__device__ void w_logm_inplace(float* B, float* t1, float* t2, float* t3,
                               float* t4, float* t5, int lane) {
    int jsq = 0;
    while (jsq < 8) {
        float d2 = w_norm2_diffI(B, lane);
        if (d2 < 0.09f) break;
        w_sqrt_inplace(B, t1, t2, t3, t4, t5, lane);
        jsq++;
    }
#pragma unroll
    for (int e = 0; e < 8; ++e) {
        int idx = e * 32 + lane; int i = idx >> 4, j = idx & 15;
        float v = B[idx] - (i == j ? 1.f : 0.f);
        t1[idx] = v; t2[idx] = v; B[idx] = v;
    }
    __syncwarp();
    float* P = t2; float* P2 = t3;
    float sgn = 1.f;
    for (int k = 2; k <= 18; ++k) {
        wmm(P2, P, t1, lane);
        sgn = -sgn;
        float coef = sgn / (float)k;
        float pn = 0.f;
#pragma unroll
        for (int e = 0; e < 8; ++e) {
            int idx = e * 32 + lane;
            float v = P2[idx]; B[idx] += coef * v; pn += v * v;
        }
        pn = wsum(pn);
        __syncwarp();
        float* tm = P; P = P2; P2 = tm;
        if (pn < 1e-13f * (float)(k * k)) break;
    }
    float f = (float)(1 << jsq);
#pragma unroll
    for (int e = 0; e < 8; ++e) B[e * 32 + lane] *= f;
    __syncwarp();
}

// =========================================================================
// K2: the whole small-matrix chain in one 128-thread block.
//   xmean -> G -> (Gs,Gi) -> 32 logm (warp-parallel) -> expm -> Karcher mean
//   -> invsqrt(mean)=C -> geodesic(running_mean, mean, 0.1)
// =========================================================================
__global__ __launch_bounds__(128) void k_small(const float* __restrict__ rm,
                                               float* __restrict__ out_tail,
                                               int write_tail) {
    __shared__ float wb[4][6][256];      // per-warp workspaces
    __shared__ float lsum[4][256];       // per-warp log-map partial sums
    __shared__ float m0[256], m1[256], m2[256], m3[256], m4[256], m5[256], m6[256];
    __shared__ float sGs[256], sGi[256], sMean[256];
    __shared__ float red[128];

    int t = threadIdx.x, w = t >> 5, lane = t & 31;

    // ---- stage 1: per-sample means from partials; arithmetic mean G ----
    for (int idx = t; idx < S_N * NE; idx += 128) {
        int b = idx >> 8, e = idx & 255;
        float acc = 0.f;
#pragma unroll 8
        for (int c = 0; c < CHUNKS; ++c) acc += g_partial[(b * CHUNKS + c) * NE + e];
        g_xmean[idx] = acc * (1.f / (float)TVM);
    }
    __syncthreads();
    {
        float a0 = 0.f, a1 = 0.f;
        for (int b = 0; b < S_N; ++b) {
            a0 += g_xmean[b * NE + t];
            a1 += g_xmean[b * NE + t + 128];
        }
        m0[t] = a0 * (1.f / (float)S_N);
        m0[t + 128] = a1 * (1.f / (float)S_N);
    }
    __syncthreads();

    // ---- stage 2: Gs = sqrt(G), Gi = invsqrt(G) ----
    b_sqrtinv(m0, sGs, sGi, m1, m2, m3, t, red);

    // ---- stage 3: L_b = logm(Gi * Xmean_b * Gi), summed (warp-parallel) ----
#pragma unroll
    for (int e = 0; e < 8; ++e) lsum[w][e * 32 + lane] = 0.f;
    __syncwarp();
    {
        float* b0 = wb[w][0]; float* b1 = wb[w][1]; float* b2 = wb[w][2];
        float* b3 = wb[w][3]; float* b4 = wb[w][4]; float* b5 = wb[w][5];
        for (int b = w; b < S_N; b += 4) {
#pragma unroll
            for (int e = 0; e < 8; ++e) b1[e * 32 + lane] = g_xmean[b * NE + e * 32 + lane];
            __syncwarp();
            wmm(b2, sGi, b1, lane);
            wmm(b0, b2, sGi, lane);
            w_logm_inplace(b0, b1, b2, b3, b4, b5, lane);
#pragma unroll
            for (int e = 0; e < 8; ++e) lsum[w][e * 32 + lane] += b0[e * 32 + lane];
            __syncwarp();
        }
    }
    __syncthreads();

    // ---- stage 4: Lbar, expm, mean = Gs * expm(Lbar) * Gs ----
#pragma unroll
    for (int e = 0; e < 2; ++e) {
        int idx = t + e * 128;
        m0[idx] = (lsum[0][idx] + lsum[1][idx] + lsum[2][idx] + lsum[3][idx]) * (1.f / (float)S_N);
    }
    __syncthreads();
    b_expm(m0, m1, m2, m3, t, red);
    bmm(m2, sGs, m1, t);
    bmm(sMean, m2, sGs, t);

    // ---- stage 5: C = invsqrt(mean) -> g_C ----
    b_sqrtinv(sMean, m4, m5, m0, m1, m2, t, red);
    g_C[t] = m5[t]; g_C[t + 128] = m5[t + 128];
    __syncthreads();

    // ---- stage 6: geodesic(running_mean, mean, 0.1) ----
    m0[t] = rm[t]; m0[t + 128] = rm[t + 128];
    __syncthreads();
    b_sqrtinv(m0, sGs, sGi, m1, m2, m3, t, red);   // As = sGs, Ai = sGi
    bmm(m1, sGi, sMean, t);
    bmm(m0, m1, sGi, t);                           // M = Ai * mean * Ai
    b_logm_inplace(m0, m1, m2, m3, m4, m5, t, red);
    m0[t] *= 0.1f; m0[t + 128] *= 0.1f;
    __syncthreads();
    b_expm(m0, m1, m2, m3, t, red);                // m1 = M^0.1
    bmm(m2, sGs, m1, t);
    bmm(m3, m2, sGs, t);                           // new running mean
    if (write_tail) {
        out_tail[t] = m3[t];
        out_tail[t + 128] = m3[t + 128];
    }
}

// =========================================================================
// K3: Y = C * X * C for all 102,400 matrices. Packed f32x2 FMA, float4 I/O.
// One thread per (matrix, row); 16 matrices per 256-thread block.
// =========================================================================
typedef unsigned long long u64;
__device__ __forceinline__ u64 pk2(float lo, float hi) {
    u64 r; asm("mov.b64 %0, {%1, %2};" : "=l"(r) : "f"(lo), "f"(hi)); return r;
}
__device__ __forceinline__ void upk2(u64 v, float& lo, float& hi) {
    asm("mov.b64 {%0, %1}, %2;" : "=f"(lo), "=f"(hi) : "l"(v));
}
__device__ __forceinline__ u64 ffma2(u64 a, u64 b, u64 c) {
    u64 d; asm("fma.rn.f32x2 %0, %1, %2, %3;" : "=l"(d) : "l"(a), "l"(b), "l"(c)); return d;
}

#define MPB  16    // matrices per block
#define ZPAD 20    // padded row stride (floats) for the Z staging tile

__global__ __launch_bounds__(256) void k_transform(const float* __restrict__ X,
                                                   float* __restrict__ Y) {
    __shared__ float Cs[256];
    __shared__ float Zs[MPB * 16 * ZPAD];
    int t = threadIdx.x;
    Cs[t] = g_C[t];
    int m = t >> 4, i = t & 15;
    size_t base = (size_t)blockIdx.x * (MPB * NE) + (size_t)m * NE + (size_t)i * 16;

    float xr[16];
    const float4* xp = (const float4*)(X + base);
#pragma unroll
    for (int q = 0; q < 4; ++q) {
        float4 v = xp[q];
        xr[4 * q] = v.x; xr[4 * q + 1] = v.y; xr[4 * q + 2] = v.z; xr[4 * q + 3] = v.w;
    }
    __syncthreads();

    // Z row i = x_row * C
    u64 acc[8];
#pragma unroll
    for (int q = 0; q < 8; ++q) acc[q] = pk2(0.f, 0.f);
#pragma unroll
    for (int k = 0; k < 16; ++k) {
        u64 vv = pk2(xr[k], xr[k]);
        const u64* crow = (const u64*)&Cs[k * 16];
#pragma unroll
        for (int q = 0; q < 8; ++q) acc[q] = ffma2(vv, crow[q], acc[q]);
    }
    float* zr = &Zs[(m * 16 + i) * ZPAD];
#pragma unroll
    for (int q = 0; q < 8; ++q) upk2(acc[q], zr[2 * q], zr[2 * q + 1]);

    float cr[16];
#pragma unroll
    for (int k = 0; k < 16; ++k) cr[k] = Cs[i * 16 + k];
    __syncthreads();

    // Y row i = C row i * Z
#pragma unroll
    for (int q = 0; q < 8; ++q) acc[q] = pk2(0.f, 0.f);
#pragma unroll
    for (int k = 0; k < 16; ++k) {
        u64 vv = pk2(cr[k], cr[k]);
        const u64* zrow = (const u64*)&Zs[(m * 16 + k) * ZPAD];
#pragma unroll
        for (int q = 0; q < 8; ++q) acc[q] = ffma2(vv, zrow[q], acc[q]);
    }
    float4* yp = (float4*)(Y + base);
#pragma unroll
    for (int q = 0; q < 4; ++q) {
        float4 v;
        upk2(acc[2 * q], v.x, v.y);
        upk2(acc[2 * q + 1], v.z, v.w);
        yp[q] = v;
    }
}

// =========================================================================
extern "C" void kernel_launch(void* const* d_in, const int* in_sizes, int n_in,
                              void* d_out, int out_size) {
    const float* X = (const float*)d_in[0];
    const float* rm = (const float*)d_in[1];
    float* out = (float*)d_out;
    long long n_x = in_sizes[0];           // 26,214,400
    int nmat = (int)(n_x >> 8);            // 102,400
    int write_tail = ((long long)out_size - n_x) >= NE ? 1 : 0;

    k_partial<<<dim3(S_N, CHUNKS), 256>>>(X);
    k_small<<<1, 128>>>(rm, out + n_x, write_tail);
    k_transform<<<nmat / MPB, 256>>>(X, out);
}

// round 3
// speedup vs baseline: 1.7355x; 1.7355x over previous
#include <cuda_runtime.h>
#include <math.h>

// Problem shape (fixed by setup_inputs): X (32, 64, 25, 2, 16, 16) fp32.
#define S_N     32     // batch N
#define TVM     3200   // 64*25*2 matrices per sample
#define NE      256    // 16*16 elements per matrix
#define CHUNKS  32     // K1 partial-reduce chunks per sample
#define CHUNK_M 100    // TVM / CHUNKS
#define SROW    20     // padded shared row stride (floats), 80B (16B-aligned rows)

// ---------------- device scratch (no allocations allowed) ----------------
__device__ float g_partial[S_N * CHUNKS * NE];
__device__ float g_xmean[S_N * NE];
__device__ float g_L[S_N * NE];
__device__ float g_Gs[NE], g_Gi[NE];   // sqrt/invsqrt of arithmetic mean G
__device__ float g_As[NE], g_Ai[NE];   // sqrt/invsqrt of running_mean
__device__ float g_C[NE];              // invsqrt(Karcher mean)

// =========================================================================
// K1: partial reduction of X. grid (32,32), 256 thr; 100 matrices per block.
// 4 accumulators to expose MLP.
// =========================================================================
__global__ __launch_bounds__(256) void k_partial(const float* __restrict__ X) {
    int s = blockIdx.x, c = blockIdx.y, t = threadIdx.x;
    const float* p = X + ((size_t)s * TVM + (size_t)c * CHUNK_M) * NE + t;
    float a0 = 0.f, a1 = 0.f, a2 = 0.f, a3 = 0.f;
#pragma unroll 5
    for (int m = 0; m < CHUNK_M; m += 4) {
        a0 += p[(size_t)m * NE];
        a1 += p[(size_t)(m + 1) * NE];
        a2 += p[(size_t)(m + 2) * NE];
        a3 += p[(size_t)(m + 3) * NE];
    }
    g_partial[(s * CHUNKS + c) * NE + t] = (a0 + a1) + (a2 + a3);
}

// =========================================================================
// K1b: per-sample means. grid 32, 256 thr.
// =========================================================================
__global__ __launch_bounds__(256) void k_samplemean() {
    int b = blockIdx.x, t = threadIdx.x;
    float acc = 0.f;
#pragma unroll 8
    for (int c = 0; c < CHUNKS; ++c) acc += g_partial[(b * CHUNKS + c) * NE + t];
    g_xmean[b * NE + t] = acc * (1.f / (float)TVM);
}

// =========================================================================
// Warp-level 16x16 matrix toolkit. One warp owns one matrix.
// Storage: shared, row stride SROW floats; element (r,c) at r*SROW+c.
// Per-lane ownership for elementwise ops: elems e = lane*8 + q, q in [0,8).
// =========================================================================
__device__ __forceinline__ int sidx(int e) { return (e >> 4) * SROW + (e & 15); }

__device__ __forceinline__ float wsum32(float v) {
#pragma unroll
    for (int o = 16; o; o >>= 1) v += __shfl_xor_sync(0xffffffffu, v, o);
    return v;
}

__device__ __forceinline__ float w_trace(const float* A, int lane) {
    float v = (lane < 16) ? A[lane * SROW + lane] : 0.f;
    return wsum32(v);
}

__device__ __forceinline__ void g2s(float* s, const float* __restrict__ g, int lane) {
#pragma unroll
    for (int q = 0; q < 8; ++q) { int e = lane * 8 + q; s[sidx(e)] = g[e]; }
    __syncwarp();
}
__device__ __forceinline__ void s2g(float* __restrict__ g, const float* s, int lane) {
#pragma unroll
    for (int q = 0; q < 8; ++q) { int e = lane * 8 + q; g[e] = s[sidx(e)]; }
}

// C = A * B. Lane computes half-row: i = lane>>1, cols jb..jb+7.
// Safe even if C aliases A or B (all reads complete before the store sync).
__device__ __forceinline__ void wmm16(float* C, const float* A, const float* B, int lane) {
    int i = lane >> 1, jb = (lane & 1) << 3;
    float a[16];
    {
        const float4* ar = (const float4*)(A + i * SROW);
        float4 v0 = ar[0], v1 = ar[1], v2 = ar[2], v3 = ar[3];
        a[0] = v0.x; a[1] = v0.y; a[2] = v0.z; a[3] = v0.w;
        a[4] = v1.x; a[5] = v1.y; a[6] = v1.z; a[7] = v1.w;
        a[8] = v2.x; a[9] = v2.y; a[10] = v2.z; a[11] = v2.w;
        a[12] = v3.x; a[13] = v3.y; a[14] = v3.z; a[15] = v3.w;
    }
    float c[8];
#pragma unroll
    for (int q = 0; q < 8; ++q) c[q] = 0.f;
#pragma unroll
    for (int k = 0; k < 16; ++k) {
        const float4* br = (const float4*)(B + k * SROW + jb);
        float4 b0 = br[0], b1 = br[1];
        float ak = a[k];
        c[0] = fmaf(ak, b0.x, c[0]); c[1] = fmaf(ak, b0.y, c[1]);
        c[2] = fmaf(ak, b0.z, c[2]); c[3] = fmaf(ak, b0.w, c[3]);
        c[4] = fmaf(ak, b1.x, c[4]); c[5] = fmaf(ak, b1.y, c[5]);
        c[6] = fmaf(ak, b1.z, c[6]); c[7] = fmaf(ak, b1.w, c[7]);
    }
    __syncwarp();
    float4* cr = (float4*)(C + i * SROW + jb);
    cr[0] = make_float4(c[0], c[1], c[2], c[3]);
    cr[1] = make_float4(c[4], c[5], c[6], c[7]);
    __syncwarp();
}

// Coupled Newton-Schulz with scalar (trace) normalization.
// Y = sqrt(A), Z = invsqrt(A). A + 5 distinct buffers.
__device__ void w_sqrtinv(const float* A, float* Y, float* Z,
                          float* T, float* Y2, float* Z2, int lane) {
    float s = w_trace(A, lane) * (1.f / 16.f);
    {   // validity check: need ||A/s - I||_F < 1 for NS convergence
        float is0 = 1.f / s, d2 = 0.f;
#pragma unroll
        for (int q = 0; q < 8; ++q) {
            int e = lane * 8 + q; int r = e >> 4, c = e & 15;
            float v = A[sidx(e)] * is0 - (r == c ? 1.f : 0.f);
            d2 += v * v;
        }
        d2 = wsum32(d2);
        if (d2 >= 0.9f) {   // Gershgorin fallback: s = max row abs-sum
            float rs = 0.f;
            if (lane < 16) {
                for (int k = 0; k < 16; ++k) rs += fabsf(A[lane * SROW + k]);
            }
#pragma unroll
            for (int o = 16; o; o >>= 1) rs = fmaxf(rs, __shfl_xor_sync(0xffffffffu, rs, o));
            s = rs;
        }
    }
    float is_ = 1.f / s;
#pragma unroll
    for (int q = 0; q < 8; ++q) {
        int e = lane * 8 + q; int r = e >> 4, c = e & 15;
        Y[sidx(e)] = A[sidx(e)] * is_;
        Z[sidx(e)] = (r == c) ? 1.f : 0.f;
    }
    __syncwarp();
    float* y = Y; float* z = Z; float* y2 = Y2; float* z2 = Z2;
    for (int it = 0; it < 25; ++it) {
        wmm16(T, z, y, lane);
        float err = 0.f;
#pragma unroll
        for (int q = 0; q < 8; ++q) {
            int e = lane * 8 + q; int r = e >> 4, c = e & 15;
            float v = T[sidx(e)] - (r == c ? 1.f : 0.f);
            err += v * v;
        }
        err = wsum32(err);
        if (err < 1e-12f) break;
#pragma unroll
        for (int q = 0; q < 8; ++q) {
            int e = lane * 8 + q; int r = e >> 4, c = e & 15;
            T[sidx(e)] = 0.5f * ((r == c ? 3.f : 0.f) - T[sidx(e)]);
        }
        __syncwarp();
        wmm16(y2, y, T, lane);
        wmm16(z2, T, z, lane);
        float* tm = y; y = y2; y2 = tm;
        tm = z; z = z2; z2 = tm;
    }
    float fs = sqrtf(s), fi = rsqrtf(s);
    float ry[8], rz[8];
#pragma unroll
    for (int q = 0; q < 8; ++q) {
        int e = lane * 8 + q;
        ry[q] = y[sidx(e)] * fs; rz[q] = z[sidx(e)] * fi;
    }
    __syncwarp();
#pragma unroll
    for (int q = 0; q < 8; ++q) {
        int e = lane * 8 + q;
        Y[sidx(e)] = ry[q]; Z[sidx(e)] = rz[q];
    }
    __syncwarp();
}

// logm(B) in place. Scalar normalization logm(B)=ln(s)I+logm(B/s) kills the
// inverse-scaling sqrts on this data; sqrt loop kept as guarded fallback.
__device__ void w_logm(float* B, float* t1, float* t2, float* t3,
                       float* t4, float* t5, int lane) {
    int jsq = 0;
    float s;
    for (;;) {
        s = w_trace(B, lane) * (1.f / 16.f);
        float is_ = 1.f / s, d2 = 0.f;
#pragma unroll
        for (int q = 0; q < 8; ++q) {
            int e = lane * 8 + q; int r = e >> 4, c = e & 15;
            float v = B[sidx(e)] * is_ - (r == c ? 1.f : 0.f);
            t1[sidx(e)] = v; d2 += v * v;
        }
        __syncwarp();
        d2 = wsum32(d2);
        if (d2 <= 0.09f || jsq >= 6) break;     // ||E||_F <= 0.3
        w_sqrtinv(B, t2, t3, t4, t5, t1, lane); // t2 = sqrt(B)
        float r8[8];
#pragma unroll
        for (int q = 0; q < 8; ++q) r8[q] = t2[sidx(lane * 8 + q)];
        __syncwarp();
#pragma unroll
        for (int q = 0; q < 8; ++q) B[sidx(lane * 8 + q)] = r8[q];
        __syncwarp();
        jsq++;
    }
    float lns = logf(s);
    // B = ln(s) I + E ; P = E (t2) ; E stays in t1
#pragma unroll
    for (int q = 0; q < 8; ++q) {
        int e = lane * 8 + q; int r = e >> 4, c = e & 15;
        float v = t1[sidx(e)];
        B[sidx(e)] = lns * (r == c ? 1.f : 0.f) + v;
        t2[sidx(e)] = v;
    }
    __syncwarp();
    float* P = t2; float* P2 = t3;
    float sg = 1.f;
    for (int k = 2; k <= 16; ++k) {
        wmm16(P2, P, t1, lane);
        sg = -sg;
        float cf = sg / (float)k, tn = 0.f;
#pragma unroll
        for (int q = 0; q < 8; ++q) {
            int e = lane * 8 + q;
            float v = P2[sidx(e)];
            B[sidx(e)] += cf * v; tn += v * v;
        }
        __syncwarp();
        tn = wsum32(tn);
        float* tm = P; P = P2; P2 = tm;
        if (tn < 1e-14f) break;
    }
    if (jsq) {
        float f = (float)(1 << jsq);
#pragma unroll
        for (int q = 0; q < 8; ++q) B[sidx(lane * 8 + q)] *= f;
        __syncwarp();
    }
}

// R = expm(A), scalar-shift expm(A)=e^c expm(A-cI), c=tr/16; squaring fallback.
// A is preserved. R + 3 temps distinct from A.
__device__ void w_expm(const float* A, float* R, float* t1, float* t2, float* t3, int lane) {
    float c0 = w_trace(A, lane) * (1.f / 16.f);
    float d2 = 0.f;
#pragma unroll
    for (int q = 0; q < 8; ++q) {
        int e = lane * 8 + q; int r = e >> 4, c = e & 15;
        float v = A[sidx(e)] - c0 * (r == c ? 1.f : 0.f);
        t1[sidx(e)] = v; d2 += v * v;
    }
    __syncwarp();
    d2 = wsum32(d2);
    int j = 0; float sc = 1.f;
    while (d2 > 0.0625f && j < 20) { sc *= 0.5f; d2 *= 0.25f; j++; }
    if (j) {
#pragma unroll
        for (int q = 0; q < 8; ++q) t1[sidx(lane * 8 + q)] *= sc;
        __syncwarp();
    }
    float ec = expf(c0 * sc);
    // S = I + E in R, term = E in t2
#pragma unroll
    for (int q = 0; q < 8; ++q) {
        int e = lane * 8 + q; int r = e >> 4, c = e & 15;
        float v = t1[sidx(e)];
        R[sidx(e)] = (r == c ? 1.f : 0.f) + v;
        t2[sidx(e)] = v;
    }
    __syncwarp();
    float* P = t2; float* P2 = t3;
    for (int k = 2; k <= 12; ++k) {
        wmm16(P2, P, t1, lane);
        float ik = 1.f / (float)k, tn = 0.f;
#pragma unroll
        for (int q = 0; q < 8; ++q) {
            int e = lane * 8 + q;
            float v = P2[sidx(e)] * ik;
            P2[sidx(e)] = v; R[sidx(e)] += v; tn += v * v;
        }
        __syncwarp();
        tn = wsum32(tn);
        float* tm = P; P = P2; P2 = tm;
        if (tn < 1e-14f) break;
    }
#pragma unroll
    for (int q = 0; q < 8; ++q) R[sidx(lane * 8 + q)] *= ec;
    __syncwarp();
    for (int q2 = 0; q2 < j; ++q2) {
        wmm16(t2, R, R, lane);
#pragma unroll
        for (int q = 0; q < 8; ++q) R[sidx(lane * 8 + q)] = t2[sidx(lane * 8 + q)];
        __syncwarp();
    }
}

// =========================================================================
// K2: G = mean_b(xmean); (Gs,Gi) = sqrt/invsqrt(G)  [warp 0]
//     (As,Ai) = sqrt/invsqrt(running_mean)          [warp 1, parallel]
// =========================================================================
__global__ __launch_bounds__(64) void k_prep(const float* __restrict__ rm) {
    __shared__ __align__(16) float ws[2][6][16 * SROW];
    int t = threadIdx.x, w = t >> 5, lane = t & 31;
    float* b0 = ws[w][0]; float* b1 = ws[w][1]; float* b2 = ws[w][2];
    float* b3 = ws[w][3]; float* b4 = ws[w][4]; float* b5 = ws[w][5];
    if (w == 0) {
#pragma unroll
        for (int q = 0; q < 8; ++q) {
            int e = lane * 8 + q;
            float acc = 0.f;
            for (int b = 0; b < S_N; ++b) acc += g_xmean[b * NE + e];
            b0[sidx(e)] = acc * (1.f / (float)S_N);
        }
        __syncwarp();
        w_sqrtinv(b0, b1, b2, b3, b4, b5, lane);
        s2g(g_Gs, b1, lane); s2g(g_Gi, b2, lane);
    } else {
        g2s(b0, rm, lane);
        w_sqrtinv(b0, b1, b2, b3, b4, b5, lane);
        s2g(g_As, b1, lane); s2g(g_Ai, b2, lane);
    }
}

// =========================================================================
// K3: L_b = logm(Gi * xmean_b * Gi), 32 blocks (one warp each) in parallel.
// =========================================================================
__global__ __launch_bounds__(32) void k_logm() {
    __shared__ __align__(16) float m[6][16 * SROW];
    int b = blockIdx.x, lane = threadIdx.x;
    g2s(m[0], g_Gi, lane);
    g2s(m[1], g_xmean + b * NE, lane);
    wmm16(m[2], m[0], m[1], lane);
    wmm16(m[3], m[2], m[0], lane);
    w_logm(m[3], m[0], m[1], m[2], m[4], m[5], lane);
    s2g(g_L + b * NE, m[3], lane);
}

// =========================================================================
// K4: mean = Gs expm(mean(L)) Gs; then in parallel:
//     warp0: C = invsqrt(mean);  warp1: geodesic(rm, mean, 0.1) -> tail out.
// =========================================================================
__global__ __launch_bounds__(64) void k_finish(float* __restrict__ out_tail, int write_tail) {
    __shared__ __align__(16) float ws[2][6][16 * SROW];
    __shared__ __align__(16) float sMean[16 * SROW];
    int t = threadIdx.x, w = t >> 5, lane = t & 31;
    float* b0 = ws[w][0]; float* b1 = ws[w][1]; float* b2 = ws[w][2];
    float* b3 = ws[w][3]; float* b4 = ws[w][4]; float* b5 = ws[w][5];
    if (w == 0) {
#pragma unroll
        for (int q = 0; q < 8; ++q) {
            int e = lane * 8 + q;
            float acc = 0.f;
            for (int b = 0; b < S_N; ++b) acc += g_L[b * NE + e];
            b0[sidx(e)] = acc * (1.f / (float)S_N);
        }
        __syncwarp();
        w_expm(b0, b1, b2, b3, b4, lane);   // b1 = expm(Lbar)
        g2s(b2, g_Gs, lane);
        wmm16(b3, b2, b1, lane);
        wmm16(sMean, b3, b2, lane);         // Karcher mean
    }
    __syncthreads();
    if (w == 0) {
        w_sqrtinv(sMean, b0, b1, b2, b3, b4, lane);
        s2g(g_C, b1, lane);                 // C = invsqrt(mean)
    } else {
        g2s(b0, g_Ai, lane);
        wmm16(b1, b0, sMean, lane);
        wmm16(b2, b1, b0, lane);            // M = Ai mean Ai
        w_logm(b2, b0, b1, b3, b4, b5, lane);
#pragma unroll
        for (int q = 0; q < 8; ++q) b2[sidx(lane * 8 + q)] *= 0.1f;
        __syncwarp();
        w_expm(b2, b0, b1, b3, b4, lane);   // b0 = M^0.1
        g2s(b1, g_As, lane);
        wmm16(b3, b1, b0, lane);
        wmm16(b4, b3, b1, lane);            // new running mean
        if (write_tail) s2g(out_tail, b4, lane);
    }
}

// =========================================================================
// K5: Y = C * X * C for all 102,400 matrices. Packed f32x2 FMA, float4 I/O.
// =========================================================================
typedef unsigned long long u64;
__device__ __forceinline__ u64 pk2(float lo, float hi) {
    u64 r; asm("mov.b64 %0, {%1, %2};" : "=l"(r) : "f"(lo), "f"(hi)); return r;
}
__device__ __forceinline__ void upk2(u64 v, float& lo, float& hi) {
    asm("mov.b64 {%0, %1}, %2;" : "=f"(lo), "=f"(hi) : "l"(v));
}
__device__ __forceinline__ u64 ffma2(u64 a, u64 b, u64 c) {
    u64 d; asm("fma.rn.f32x2 %0, %1, %2, %3;" : "=l"(d) : "l"(a), "l"(b), "l"(c)); return d;
}

#define MPB  16
#define ZPAD 20

__global__ __launch_bounds__(256) void k_transform(const float* __restrict__ X,
                                                   float* __restrict__ Y) {
    __shared__ float Cs[256];
    __shared__ float Zs[MPB * 16 * ZPAD];
    int t = threadIdx.x;
    Cs[t] = g_C[t];
    int m = t >> 4, i = t & 15;
    size_t base = (size_t)blockIdx.x * (MPB * NE) + (size_t)m * NE + (size_t)i * 16;

    float xr[16];
    const float4* xp = (const float4*)(X + base);
#pragma unroll
    for (int q = 0; q < 4; ++q) {
        float4 v = xp[q];
        xr[4 * q] = v.x; xr[4 * q + 1] = v.y; xr[4 * q + 2] = v.z; xr[4 * q + 3] = v.w;
    }
    __syncthreads();

    u64 acc[8];
#pragma unroll
    for (int q = 0; q < 8; ++q) acc[q] = pk2(0.f, 0.f);
#pragma unroll
    for (int k = 0; k < 16; ++k) {
        u64 vv = pk2(xr[k], xr[k]);
        const u64* crow = (const u64*)&Cs[k * 16];
#pragma unroll
        for (int q = 0; q < 8; ++q) acc[q] = ffma2(vv, crow[q], acc[q]);
    }
    float* zr = &Zs[(m * 16 + i) * ZPAD];
#pragma unroll
    for (int q = 0; q < 8; ++q) upk2(acc[q], zr[2 * q], zr[2 * q + 1]);

    float cr[16];
#pragma unroll
    for (int k = 0; k < 16; ++k) cr[k] = Cs[i * 16 + k];
    __syncthreads();

#pragma unroll
    for (int q = 0; q < 8; ++q) acc[q] = pk2(0.f, 0.f);
#pragma unroll
    for (int k = 0; k < 16; ++k) {
        u64 vv = pk2(cr[k], cr[k]);
        const u64* zrow = (const u64*)&Zs[(m * 16 + k) * ZPAD];
#pragma unroll
        for (int q = 0; q < 8; ++q) acc[q] = ffma2(vv, zrow[q], acc[q]);
    }
    float4* yp = (float4*)(Y + base);
#pragma unroll
    for (int q = 0; q < 4; ++q) {
        float4 v;
        upk2(acc[2 * q], v.x, v.y);
        upk2(acc[2 * q + 1], v.z, v.w);
        yp[q] = v;
    }
}

// =========================================================================
extern "C" void kernel_launch(void* const* d_in, const int* in_sizes, int n_in,
                              void* d_out, int out_size) {
    const float* X = (const float*)d_in[0];
    const float* rm = (const float*)d_in[1];
    float* out = (float*)d_out;
    long long n_x = in_sizes[0];           // 26,214,400
    int nmat = (int)(n_x >> 8);            // 102,400
    int write_tail = ((long long)out_size - n_x) >= NE ? 1 : 0;

    k_partial<<<dim3(S_N, CHUNKS), 256>>>(X);
    k_samplemean<<<S_N, 256>>>();
    k_prep<<<1, 64>>>(rm);
    k_logm<<<S_N, 32>>>();
    k_finish<<<1, 64>>>(out + n_x, write_tail);
    k_transform<<<nmat / MPB, 256>>>(X, out);
}